// round 1
// baseline (speedup 1.0000x reference)
#include <cuda_runtime.h>

#define NB      96
#define MTILE   16
#define THREADS 128

// ---- packed f32x2 helpers (sm_100+/sm_103a) ----
__device__ __forceinline__ unsigned long long pack2(float x, float y) {
    unsigned long long r;
    asm("mov.b64 %0, {%1, %2};" : "=l"(r) : "f"(x), "f"(y));
    return r;
}
__device__ __forceinline__ void unpack2(unsigned long long v, float& x, float& y) {
    asm("mov.b64 {%0, %1}, %2;" : "=f"(x), "=f"(y) : "l"(v));
}
__device__ __forceinline__ void ffma2(unsigned long long& d, unsigned long long a, unsigned long long b) {
    asm("fma.rn.f32x2 %0, %1, %2, %0;" : "+l"(d) : "l"(a), "l"(b));
}

__global__ __launch_bounds__(THREADS, 4)
void net_kernel(const float* __restrict__ X,      // policy_in_c [8192][96][4]
                const float* __restrict__ TN,     // trans_noise [8192][96]
                const float* __restrict__ DN,     // demand_noise [8192][96]
                const float* __restrict__ A0,     // action_pre [8192]
                const float* __restrict__ S0,     // state_pre  [8192]
                const float* __restrict__ LAM,    // Lambda [1]
                const float* __restrict__ BUD,    // Budget [1]
                const float* __restrict__ W1,     // [256][6]
                const float* __restrict__ B1,     // [256]
                const float* __restrict__ W2,     // [256][256]
                const float* __restrict__ B2,     // [256]
                const float* __restrict__ W3,     // [256]
                const float* __restrict__ B3,     // [1]
                float* __restrict__ OUT)          // [8192][96]
{
    __shared__ __align__(16) float h1s[256 * MTILE];   // 16 KB, layout [j][m]
    __shared__ float W1s[256 * 6];
    __shared__ float B1s[256];
    __shared__ float feats[4][MTILE];
    __shared__ float red[4][MTILE];
    __shared__ float actS[MTILE], stS[MTILE], bgtS[MTILE],
                     cumcS[MTILE], adpS[MTILE], SS[MTILE];

    const int k    = threadIdx.x;       // 0..127
    const int lane = k & 31;
    const int warp = k >> 5;
    const int m_h1 = k & 15;            // batch slot this thread serves in layer-1
    const int r_h1 = k >> 4;            // 0..7 row-group in layer-1
    const int base = blockIdx.x * MTILE;

    // small weights into shared
    for (int i = k; i < 256 * 6; i += THREADS) W1s[i] = W1[i];
    for (int i = k; i < 256;     i += THREADS) B1s[i] = B1[i];

    const int   kA  = k, kB = k + 128;  // the two W2 rows this thread owns
    const float b2a = B2[kA], b2b = B2[kB];
    const float w3a = W3[kA], w3b = W3[kB];
    const float b3v = B3[0];
    const float lam = LAM[0], bud = BUD[0];
    const float budH     = __fdiv_rn(bud, 96.0f);
    const float per_step = lam * 2.0f + budH;

    if (k < MTILE) {
        actS[k]  = A0[base + k];
        stS[k]   = S0[base + k];
        bgtS[k]  = per_step;
        cumcS[k] = 0.0f;
        adpS[k]  = 0.0f;
        SS[k]    = 0.0f;
    }

    const float4* w2a4 = reinterpret_cast<const float4*>(W2 + (size_t)kA * 256);
    const float4* w2b4 = reinterpret_cast<const float4*>(W2 + (size_t)kB * 256);

    __syncthreads();

    for (int t = 0; t < NB; t++) {
        // ---- stage the 4 per-step features ----
        if (k < 4 * MTILE) {
            int m = k >> 2, c = k & 3;
            feats[c][m] = X[(size_t)(base + m) * (NB * 4) + t * 4 + c];
        }
        __syncthreads();

        // ---- layer 1: h1[j][m] = relu(W1[j] . x_m + b1[j]) ----
        // transposed assignment -> bank-conflict-free stores into h1s[j][m]
        {
            const float x0 = feats[0][m_h1], x1 = feats[1][m_h1],
                        x2 = feats[2][m_h1], x3 = feats[3][m_h1],
                        x4 = actS[m_h1],     x5 = stS[m_h1];
            #pragma unroll 4
            for (int i = 0; i < 32; i++) {
                int j = r_h1 + (i << 3);
                const float* w = &W1s[j * 6];
                float s = B1s[j];
                s = fmaf(w[0], x0, s);
                s = fmaf(w[1], x1, s);
                s = fmaf(w[2], x2, s);
                s = fmaf(w[3], x3, s);
                s = fmaf(w[4], x4, s);
                s = fmaf(w[5], x5, s);
                h1s[j * MTILE + m_h1] = fmaxf(s, 0.0f);
            }
        }
        __syncthreads();

        // ---- layer 2 (bulk): 2 rows x 16 elements per thread, packed f32x2 ----
        unsigned long long accA[8], accB[8];
        {
            const unsigned long long bpa = pack2(b2a, b2a);
            const unsigned long long bpb = pack2(b2b, b2b);
            #pragma unroll
            for (int p = 0; p < 8; p++) { accA[p] = bpa; accB[p] = bpb; }
        }
        #pragma unroll 2
        for (int j4 = 0; j4 < 64; j4++) {
            float4 wa = w2a4[j4];
            float4 wb = w2b4[j4];
            #pragma unroll
            for (int u = 0; u < 4; u++) {
                const float wau = (&wa.x)[u];
                const float wbu = (&wb.x)[u];
                unsigned long long wpa = pack2(wau, wau);
                unsigned long long wpb = pack2(wbu, wbu);
                const ulonglong2* hp =
                    reinterpret_cast<const ulonglong2*>(&h1s[(j4 * 4 + u) * MTILE]);
                #pragma unroll
                for (int g = 0; g < 4; g++) {
                    ulonglong2 hv = hp[g];     // 4 floats = elements 4g..4g+3
                    ffma2(accA[2 * g],     wpa, hv.x);
                    ffma2(accA[2 * g + 1], wpa, hv.y);
                    ffma2(accB[2 * g],     wpb, hv.x);
                    ffma2(accB[2 * g + 1], wpb, hv.y);
                }
            }
        }

        // ---- layer 3 partials: c[m] = w3a*relu(h2A[m]) + w3b*relu(h2B[m]) ----
        float c[MTILE];
        #pragma unroll
        for (int p = 0; p < 8; p++) {
            float a0, a1, b0, b1f;
            unpack2(accA[p], a0, a1);
            unpack2(accB[p], b0, b1f);
            c[2 * p]     = w3a * fmaxf(a0, 0.0f) + w3b * fmaxf(b0, 0.0f);
            c[2 * p + 1] = w3a * fmaxf(a1, 0.0f) + w3b * fmaxf(b1f, 0.0f);
        }
        #pragma unroll
        for (int off = 16; off >= 1; off >>= 1) {
            #pragma unroll
            for (int m = 0; m < MTILE; m++)
                c[m] += __shfl_xor_sync(0xFFFFFFFFu, c[m], off);
        }
        if (lane == 0) {
            #pragma unroll
            for (int m = 0; m < MTILE; m++) red[warp][m] = c[m];
        }
        __syncthreads();

        // ---- scalar recurrence: one thread per batch element ----
        if (k < MTILE) {
            const int m = k;
            float a_ml = red[0][m] + red[1][m] + red[2][m] + red[3][m] + b3v;
            a_ml = fmaxf(a_ml, 0.0f);

            float state_ = stS[m];
            float demand = feats[0][m];
            float a_prior = fminf(__fdiv_rn(fmaxf(state_ + demand, 0.0f), 0.8f), 10.0f);

            // p = 0.25^(95-t), exact power of two
            int n = 95 - t;
            float p = (n <= 63) ? __uint_as_float((unsigned)(127 - 2 * n) << 23) : 0.0f;
            float Gamma = 2.0f + 0.5f * (1.0f - p);

            float bgt = bgtS[m];
            float sgn = (a_ml < a_prior) ? 1.0f : -1.0f;
            float a_out = a_ml +
                fmaxf(fabsf(a_ml - a_prior) - __fdiv_rn(bgt, Gamma), 0.0f) * sgn;

            float noise  = TN[(size_t)(base + m) * NB + t];
            float noise2 = DN[(size_t)(base + m) * NB + t];
            float ns = fminf(fmaxf(state_ * (1.0f - noise2) + demand
                                   - (0.8f + noise) * a_out, 0.0f), 15.0f);
            float c_cost = 0.1f * ns * ns + ns + 2.0f;

            float ad_new = fabsf(a_out - a_prior);
            float Sold = SS[m];
            float Snew = 0.25f * Sold + ad_new;           // S_{t+1}
            float cum_d = 2.0f * ad_new + 0.375f * Sold;  // dev . q_col
            float c_prior = fmaxf(2.0f, c_cost - cum_d);
            float cum_c = cumcS[m];
            float cum_c_new = cum_c + (1.0f + lam) * c_prior - c_cost;
            float cum_d_g = 0.5f * Snew * (1.0f - p);     // dev . g_col

            float bgt_if = fmaxf(fmaxf(bgt + per_step - ad_new * Gamma, 0.0f),
                                 cum_c_new - cum_d_g + lam * 2.0f + budH * (float)(t + 2));
            float bgt_else = fmaxf(bgt + per_step - adpS[m] * Gamma, 0.0f);

            bool last = (t == NB - 1);
            bgtS[m]  = last ? bgt_else : bgt_if;
            cumcS[m] = last ? cum_c : cum_c_new;
            adpS[m]  = ad_new;
            actS[m]  = a_out;
            stS[m]   = ns;
            SS[m]    = Snew;
            OUT[(size_t)(base + m) * NB + t] = a_out;
        }
        __syncthreads();
    }
}

extern "C" void kernel_launch(void* const* d_in, const int* in_sizes, int n_in,
                              void* d_out, int out_size) {
    (void)in_sizes; (void)n_in; (void)out_size;
    net_kernel<<<512, THREADS>>>(
        (const float*)d_in[0],   // policy_in_c
        (const float*)d_in[1],   // trans_noise
        (const float*)d_in[2],   // demand_noise
        (const float*)d_in[3],   // action_pre
        (const float*)d_in[4],   // state_pre
        (const float*)d_in[5],   // Lambda
        (const float*)d_in[6],   // Budget
        (const float*)d_in[7],   // W1
        (const float*)d_in[8],   // b1
        (const float*)d_in[9],   // W2
        (const float*)d_in[10],  // b2
        (const float*)d_in[11],  // W3
        (const float*)d_in[12],  // b3
        (float*)d_out);
}

// round 2
// speedup vs baseline: 1.6401x; 1.6401x over previous
#include <cuda_runtime.h>

#define NB      96
#define MTILE   16
#define THREADS 128

// ---- packed f32x2 helpers (sm_100+/sm_103a) ----
__device__ __forceinline__ unsigned long long pack2(float x, float y) {
    unsigned long long r;
    asm("mov.b64 %0, {%1, %2};" : "=l"(r) : "f"(x), "f"(y));
    return r;
}
__device__ __forceinline__ void unpack2(unsigned long long v, float& x, float& y) {
    asm("mov.b64 {%0, %1}, %2;" : "=f"(x), "=f"(y) : "l"(v));
}
__device__ __forceinline__ void ffma2(unsigned long long& d, unsigned long long a, unsigned long long b) {
    asm("fma.rn.f32x2 %0, %1, %2, %0;" : "+l"(d) : "l"(a), "l"(b));
}

__global__ __launch_bounds__(THREADS, 4)
void net_kernel(const float* __restrict__ X,      // policy_in_c [8192][96][4]
                const float* __restrict__ TN,     // trans_noise [8192][96]
                const float* __restrict__ DN,     // demand_noise [8192][96]
                const float* __restrict__ A0,     // action_pre [8192]
                const float* __restrict__ S0,     // state_pre  [8192]
                const float* __restrict__ LAM,    // Lambda [1]
                const float* __restrict__ BUD,    // Budget [1]
                const float* __restrict__ W1,     // [256][6]
                const float* __restrict__ B1,     // [256]
                const float* __restrict__ W2,     // [256][256]
                const float* __restrict__ B2,     // [256]
                const float* __restrict__ W3,     // [256]
                const float* __restrict__ B3,     // [1]
                float* __restrict__ OUT)          // [8192][96]
{
    __shared__ __align__(16) float h1s[256 * MTILE];   // 16 KB, layout [j][m]
    __shared__ float W1s[256 * 6];
    __shared__ float B1s[256];
    __shared__ float feats[4][MTILE];
    __shared__ float red[4][MTILE];
    __shared__ float actS[MTILE], stS[MTILE], bgtS[MTILE],
                     cumcS[MTILE], adpS[MTILE], SS[MTILE];

    const int k    = threadIdx.x;       // 0..127
    const int lane = k & 31;
    const int warp = k >> 5;
    const int m_h1 = k & 15;            // batch slot this thread serves in layer-1
    const int r_h1 = k >> 4;            // 0..7 row-group in layer-1
    const int base = blockIdx.x * MTILE;

    // small weights into shared
    for (int i = k; i < 256 * 6; i += THREADS) W1s[i] = W1[i];
    for (int i = k; i < 256;     i += THREADS) B1s[i] = B1[i];

    const int   kA  = k, kB = k + 128;  // the two W2 rows this thread owns
    const float b2a = B2[kA], b2b = B2[kB];
    const float w3a = W3[kA], w3b = W3[kB];
    const float b3v = B3[0];
    const float lam = LAM[0], bud = BUD[0];
    const float budH     = __fdiv_rn(bud, 96.0f);
    const float per_step = lam * 2.0f + budH;

    if (k < MTILE) {
        actS[k]  = A0[base + k];
        stS[k]   = S0[base + k];
        bgtS[k]  = per_step;
        cumcS[k] = 0.0f;
        adpS[k]  = 0.0f;
        SS[k]    = 0.0f;
    }

    const float4* w2a4 = reinterpret_cast<const float4*>(W2 + (size_t)kA * 256);
    const float4* w2b4 = reinterpret_cast<const float4*>(W2 + (size_t)kB * 256);

    __syncthreads();

    for (int t = 0; t < NB; t++) {
        // ---- stage the 4 per-step features ----
        if (k < 4 * MTILE) {
            int m = k >> 2, c = k & 3;
            feats[c][m] = X[(size_t)(base + m) * (NB * 4) + t * 4 + c];
        }
        __syncthreads();

        // ---- layer 1: h1[j][m] = relu(W1[j] . x_m + b1[j]) ----
        // transposed assignment -> bank-conflict-free stores into h1s[j][m]
        {
            const float x0 = feats[0][m_h1], x1 = feats[1][m_h1],
                        x2 = feats[2][m_h1], x3 = feats[3][m_h1],
                        x4 = actS[m_h1],     x5 = stS[m_h1];
            #pragma unroll 4
            for (int i = 0; i < 32; i++) {
                int j = r_h1 + (i << 3);
                const float* w = &W1s[j * 6];
                float s = B1s[j];
                s = fmaf(w[0], x0, s);
                s = fmaf(w[1], x1, s);
                s = fmaf(w[2], x2, s);
                s = fmaf(w[3], x3, s);
                s = fmaf(w[4], x4, s);
                s = fmaf(w[5], x5, s);
                h1s[j * MTILE + m_h1] = fmaxf(s, 0.0f);
            }
        }
        __syncthreads();

        // ---- layer 2 (bulk): 2 rows x 16 elements per thread, packed f32x2 ----
        unsigned long long accA[8], accB[8];
        {
            const unsigned long long bpa = pack2(b2a, b2a);
            const unsigned long long bpb = pack2(b2b, b2b);
            #pragma unroll
            for (int p = 0; p < 8; p++) { accA[p] = bpa; accB[p] = bpb; }
        }
        #pragma unroll 2
        for (int j4 = 0; j4 < 64; j4++) {
            float4 wa = w2a4[j4];
            float4 wb = w2b4[j4];
            #pragma unroll
            for (int u = 0; u < 4; u++) {
                const float wau = (&wa.x)[u];
                const float wbu = (&wb.x)[u];
                unsigned long long wpa = pack2(wau, wau);
                unsigned long long wpb = pack2(wbu, wbu);
                const ulonglong2* hp =
                    reinterpret_cast<const ulonglong2*>(&h1s[(j4 * 4 + u) * MTILE]);
                #pragma unroll
                for (int g = 0; g < 4; g++) {
                    ulonglong2 hv = hp[g];     // 4 floats = elements 4g..4g+3
                    ffma2(accA[2 * g],     wpa, hv.x);
                    ffma2(accA[2 * g + 1], wpa, hv.y);
                    ffma2(accB[2 * g],     wpb, hv.x);
                    ffma2(accB[2 * g + 1], wpb, hv.y);
                }
            }
        }

        // ---- layer 3 partials: c[m] = w3a*relu(h2A[m]) + w3b*relu(h2B[m]) ----
        float c[MTILE];
        #pragma unroll
        for (int p = 0; p < 8; p++) {
            float a0, a1, b0, b1f;
            unpack2(accA[p], a0, a1);
            unpack2(accB[p], b0, b1f);
            c[2 * p]     = w3a * fmaxf(a0, 0.0f) + w3b * fmaxf(b0, 0.0f);
            c[2 * p + 1] = w3a * fmaxf(a1, 0.0f) + w3b * fmaxf(b1f, 0.0f);
        }
        #pragma unroll
        for (int off = 16; off >= 1; off >>= 1) {
            #pragma unroll
            for (int m = 0; m < MTILE; m++)
                c[m] += __shfl_xor_sync(0xFFFFFFFFu, c[m], off);
        }
        if (lane == 0) {
            #pragma unroll
            for (int m = 0; m < MTILE; m++) red[warp][m] = c[m];
        }
        __syncthreads();

        // ---- scalar recurrence: one thread per batch element ----
        if (k < MTILE) {
            const int m = k;
            float a_ml = red[0][m] + red[1][m] + red[2][m] + red[3][m] + b3v;
            a_ml = fmaxf(a_ml, 0.0f);

            float state_ = stS[m];
            float demand = feats[0][m];
            float a_prior = fminf(__fdiv_rn(fmaxf(state_ + demand, 0.0f), 0.8f), 10.0f);

            // p = 0.25^(95-t), exact power of two
            int n = 95 - t;
            float p = (n <= 63) ? __uint_as_float((unsigned)(127 - 2 * n) << 23) : 0.0f;
            float Gamma = 2.0f + 0.5f * (1.0f - p);

            float bgt = bgtS[m];
            float sgn = (a_ml < a_prior) ? 1.0f : -1.0f;
            float a_out = a_ml +
                fmaxf(fabsf(a_ml - a_prior) - __fdiv_rn(bgt, Gamma), 0.0f) * sgn;

            float noise  = TN[(size_t)(base + m) * NB + t];
            float noise2 = DN[(size_t)(base + m) * NB + t];
            float ns = fminf(fmaxf(state_ * (1.0f - noise2) + demand
                                   - (0.8f + noise) * a_out, 0.0f), 15.0f);
            float c_cost = 0.1f * ns * ns + ns + 2.0f;

            float ad_new = fabsf(a_out - a_prior);
            float Sold = SS[m];
            float Snew = 0.25f * Sold + ad_new;           // S_{t+1}
            float cum_d = 2.0f * ad_new + 0.375f * Sold;  // dev . q_col
            float c_prior = fmaxf(2.0f, c_cost - cum_d);
            float cum_c = cumcS[m];
            float cum_c_new = cum_c + (1.0f + lam) * c_prior - c_cost;
            float cum_d_g = 0.5f * Snew * (1.0f - p);     // dev . g_col

            float bgt_if = fmaxf(fmaxf(bgt + per_step - ad_new * Gamma, 0.0f),
                                 cum_c_new - cum_d_g + lam * 2.0f + budH * (float)(t + 2));
            float bgt_else = fmaxf(bgt + per_step - adpS[m] * Gamma, 0.0f);

            bool last = (t == NB - 1);
            bgtS[m]  = last ? bgt_else : bgt_if;
            cumcS[m] = last ? cum_c : cum_c_new;
            adpS[m]  = ad_new;
            actS[m]  = a_out;
            stS[m]   = ns;
            SS[m]    = Snew;
            OUT[(size_t)(base + m) * NB + t] = a_out;
        }
        __syncthreads();
    }
}

extern "C" void kernel_launch(void* const* d_in, const int* in_sizes, int n_in,
                              void* d_out, int out_size) {
    (void)in_sizes; (void)n_in; (void)out_size;
    net_kernel<<<512, THREADS>>>(
        (const float*)d_in[0],   // policy_in_c
        (const float*)d_in[1],   // trans_noise
        (const float*)d_in[2],   // demand_noise
        (const float*)d_in[3],   // action_pre
        (const float*)d_in[4],   // state_pre
        (const float*)d_in[5],   // Lambda
        (const float*)d_in[6],   // Budget
        (const float*)d_in[7],   // W1
        (const float*)d_in[8],   // b1
        (const float*)d_in[9],   // W2
        (const float*)d_in[10],  // b2
        (const float*)d_in[11],  // W3
        (const float*)d_in[12],  // b3
        (float*)d_out);
}

// round 3
// speedup vs baseline: 2.9826x; 1.8185x over previous
#include <cuda_runtime.h>

#define NB      96
#define MTILE   16
#define THREADS 128

// W2 transposed: W2I[i*256 + j] = W2[j*256 + i]
__device__ float W2I[256 * 256];

// ---- packed f32x2 helpers (sm_103a) ----
__device__ __forceinline__ unsigned long long pack2(float x, float y) {
    unsigned long long r;
    asm("mov.b64 %0, {%1, %2};" : "=l"(r) : "f"(x), "f"(y));
    return r;
}
__device__ __forceinline__ void unpack2(unsigned long long v, float& x, float& y) {
    asm("mov.b64 {%0, %1}, %2;" : "=f"(x), "=f"(y) : "l"(v));
}
__device__ __forceinline__ void ffma2(unsigned long long& d, unsigned long long a, unsigned long long b) {
    asm("fma.rn.f32x2 %0, %1, %2, %0;" : "+l"(d) : "l"(a), "l"(b));
}

__global__ void transpose_kernel(const float* __restrict__ W2) {
    int j = blockIdx.x;     // original row
    int i = threadIdx.x;    // original col (coalesced read)
    W2I[i * 256 + j] = W2[j * 256 + i];
}

__global__ __launch_bounds__(THREADS, 4)
void net_kernel(const float* __restrict__ X,      // policy_in_c [8192][96][4]
                const float* __restrict__ TN,     // trans_noise [8192][96]
                const float* __restrict__ DN,     // demand_noise [8192][96]
                const float* __restrict__ A0,     // action_pre [8192]
                const float* __restrict__ S0,     // state_pre  [8192]
                const float* __restrict__ LAM,    // Lambda [1]
                const float* __restrict__ BUD,    // Budget [1]
                const float* __restrict__ W1,     // [256][6]
                const float* __restrict__ B1,     // [256]
                const float* __restrict__ B2,     // [256]
                const float* __restrict__ W3,     // [256]
                const float* __restrict__ B3,     // [1]
                float* __restrict__ OUT)          // [8192][96]
{
    __shared__ __align__(16) float h1s[256 * MTILE];   // [i][m], 16 KB
    __shared__ float W1s[256 * 6];
    __shared__ float B1s[256];
    __shared__ float feats[4][MTILE];
    __shared__ float red[4][MTILE];
    __shared__ float outS[MTILE][NB];                  // 6 KB
    __shared__ float actS[MTILE], stS[MTILE], bgtS[MTILE],
                     cumcS[MTILE], adpS[MTILE], SS[MTILE];

    const int k    = threadIdx.x;      // 0..127
    const int lane = k & 31;
    const int warp = k >> 5;
    const int jg   = lane >> 1;        // 0..15
    const int mg   = lane & 1;         // 0..1
    const int m_h1 = k & 15;
    const int r_h1 = k >> 4;
    const int base = blockIdx.x * MTILE;
    const int jbase = warp * 64 + jg * 4;   // first of this lane's 4 output rows

    for (int i = k; i < 256 * 6; i += THREADS) W1s[i] = W1[i];
    for (int i = k; i < 256;     i += THREADS) B1s[i] = B1[i];

    float b2r[4], w3r[4];
    #pragma unroll
    for (int j = 0; j < 4; j++) { b2r[j] = B2[jbase + j]; w3r[j] = W3[jbase + j]; }
    const float b3v = B3[0];
    const float lam = LAM[0], bud = BUD[0];
    const float budH     = __fdiv_rn(bud, 96.0f);
    const float per_step = lam * 2.0f + budH;

    if (k < MTILE) {
        actS[k]  = A0[base + k];
        stS[k]   = S0[base + k];
        bgtS[k]  = per_step;
        cumcS[k] = 0.0f;
        adpS[k]  = 0.0f;
        SS[k]    = 0.0f;
    }
    __syncthreads();

    const char* hC = reinterpret_cast<const char*>(h1s) + mg * 32;

    for (int t = 0; t < NB; t++) {
        // ---- stage features ----
        if (k < 4 * MTILE) {
            int m = k >> 2, c = k & 3;
            feats[c][m] = X[(size_t)(base + m) * (NB * 4) + t * 4 + c];
        }
        __syncthreads();

        // ---- layer 1: h1s[i][m] = relu(W1[i].x_m + b1[i]) ----
        {
            const float x0 = feats[0][m_h1], x1 = feats[1][m_h1],
                        x2 = feats[2][m_h1], x3 = feats[3][m_h1],
                        x4 = actS[m_h1],     x5 = stS[m_h1];
            #pragma unroll 4
            for (int ii = 0; ii < 32; ii++) {
                int j = r_h1 + (ii << 3);
                const float* w = &W1s[j * 6];
                float s = B1s[j];
                s = fmaf(w[0], x0, s);
                s = fmaf(w[1], x1, s);
                s = fmaf(w[2], x2, s);
                s = fmaf(w[3], x3, s);
                s = fmaf(w[4], x4, s);
                s = fmaf(w[5], x5, s);
                h1s[j * MTILE + m_h1] = fmaxf(s, 0.0f);
            }
        }
        __syncthreads();

        // ---- layer 2: 4 j-rows x 8 m per lane, packed f32x2 ----
        unsigned long long acc[16];
        #pragma unroll
        for (int j = 0; j < 4; j++) {
            unsigned long long bp = pack2(b2r[j], b2r[j]);
            acc[j * 4 + 0] = bp; acc[j * 4 + 1] = bp;
            acc[j * 4 + 2] = bp; acc[j * 4 + 3] = bp;
        }
        const float* wp0 = W2I + jbase;
        #pragma unroll 4
        for (int i = 0; i < 256; i++) {
            float4 wv = *reinterpret_cast<const float4*>(wp0 + i * 256);
            ulonglong2 ha = *reinterpret_cast<const ulonglong2*>(hC + i * 64);
            ulonglong2 hb = *reinterpret_cast<const ulonglong2*>(hC + i * 64 + 16);
            #pragma unroll
            for (int j = 0; j < 4; j++) {
                const float wj = (&wv.x)[j];
                unsigned long long wpk = pack2(wj, wj);
                ffma2(acc[j * 4 + 0], wpk, ha.x);
                ffma2(acc[j * 4 + 1], wpk, ha.y);
                ffma2(acc[j * 4 + 2], wpk, hb.x);
                ffma2(acc[j * 4 + 3], wpk, hb.y);
            }
        }

        // ---- layer 3 partials over this lane's 4 rows ----
        float cm[8];
        #pragma unroll
        for (int q = 0; q < 8; q++) cm[q] = 0.0f;
        #pragma unroll
        for (int j = 0; j < 4; j++) {
            #pragma unroll
            for (int p = 0; p < 4; p++) {
                float v0, v1;
                unpack2(acc[j * 4 + p], v0, v1);
                cm[2 * p]     = fmaf(w3r[j], fmaxf(v0, 0.0f), cm[2 * p]);
                cm[2 * p + 1] = fmaf(w3r[j], fmaxf(v1, 0.0f), cm[2 * p + 1]);
            }
        }
        // reduce across jg (butterfly over lane bits 1..4)
        #pragma unroll
        for (int off = 2; off <= 16; off <<= 1) {
            #pragma unroll
            for (int q = 0; q < 8; q++)
                cm[q] += __shfl_xor_sync(0xFFFFFFFFu, cm[q], off);
        }
        if (jg == 0) {  // lanes 0 (mg=0) and 1 (mg=1)
            #pragma unroll
            for (int q = 0; q < 8; q++) red[warp][mg * 8 + q] = cm[q];
        }
        __syncthreads();

        // ---- scalar recurrence ----
        if (k < MTILE) {
            const int m = k;
            float a_ml = red[0][m] + red[1][m] + red[2][m] + red[3][m] + b3v;
            a_ml = fmaxf(a_ml, 0.0f);

            float state_ = stS[m];
            float demand = feats[0][m];
            float a_prior = fminf(__fdiv_rn(fmaxf(state_ + demand, 0.0f), 0.8f), 10.0f);

            int n = 95 - t;
            float p = (n <= 63) ? __uint_as_float((unsigned)(127 - 2 * n) << 23) : 0.0f;
            float Gamma = 2.0f + 0.5f * (1.0f - p);

            float bgt = bgtS[m];
            float sgn = (a_ml < a_prior) ? 1.0f : -1.0f;
            float a_out = a_ml +
                fmaxf(fabsf(a_ml - a_prior) - __fdiv_rn(bgt, Gamma), 0.0f) * sgn;

            float noise  = TN[(size_t)(base + m) * NB + t];
            float noise2 = DN[(size_t)(base + m) * NB + t];
            float ns = fminf(fmaxf(state_ * (1.0f - noise2) + demand
                                   - (0.8f + noise) * a_out, 0.0f), 15.0f);
            float c_cost = 0.1f * ns * ns + ns + 2.0f;

            float ad_new = fabsf(a_out - a_prior);
            float Sold = SS[m];
            float Snew = 0.25f * Sold + ad_new;
            float cum_d = 2.0f * ad_new + 0.375f * Sold;
            float c_prior = fmaxf(2.0f, c_cost - cum_d);
            float cum_c = cumcS[m];
            float cum_c_new = cum_c + (1.0f + lam) * c_prior - c_cost;
            float cum_d_g = 0.5f * Snew * (1.0f - p);

            float bgt_if = fmaxf(fmaxf(bgt + per_step - ad_new * Gamma, 0.0f),
                                 cum_c_new - cum_d_g + lam * 2.0f + budH * (float)(t + 2));
            float bgt_else = fmaxf(bgt + per_step - adpS[m] * Gamma, 0.0f);

            bool last = (t == NB - 1);
            bgtS[m]  = last ? bgt_else : bgt_if;
            cumcS[m] = last ? cum_c : cum_c_new;
            adpS[m]  = ad_new;
            actS[m]  = a_out;
            stS[m]   = ns;
            SS[m]    = Snew;
            outS[m][t] = a_out;
        }
        __syncthreads();
    }

    // ---- coalesced output flush ----
    for (int idx = k; idx < MTILE * NB; idx += THREADS) {
        int m = idx / NB, t = idx - m * NB;
        OUT[(size_t)(base + m) * NB + t] = outS[m][t];
    }
}

extern "C" void kernel_launch(void* const* d_in, const int* in_sizes, int n_in,
                              void* d_out, int out_size) {
    (void)in_sizes; (void)n_in; (void)out_size;
    transpose_kernel<<<256, 256>>>((const float*)d_in[9]);   // W2
    net_kernel<<<512, THREADS>>>(
        (const float*)d_in[0],   // policy_in_c
        (const float*)d_in[1],   // trans_noise
        (const float*)d_in[2],   // demand_noise
        (const float*)d_in[3],   // action_pre
        (const float*)d_in[4],   // state_pre
        (const float*)d_in[5],   // Lambda
        (const float*)d_in[6],   // Budget
        (const float*)d_in[7],   // W1
        (const float*)d_in[8],   // b1
        (const float*)d_in[10],  // b2
        (const float*)d_in[11],  // W3
        (const float*)d_in[12],  // b3
        (float*)d_out);
}